// round 8
// baseline (speedup 1.0000x reference)
#include <cuda_runtime.h>
#include <cuda_bf16.h>
#include <stdint.h>
#include <math.h>

// TriangularSylvesterNeRF  Z=32 K=4 H=128 B=32768
// mma.sync bf16 split-precision, warp-specialized (8 GEMM warps + 4 flow warps),
// 32x32 warp tiles to halve smem B traffic. DP=136 for 16B alignment.

#define ZZ 32
#define KK 4
#define HH 128
#define TM 64
#define NTH 384
#define NGT 256          /* gemm threads */
#define NCTA 512
#define DP 136           /* D row pitch (floats), multiple of 8 */

// ---- smem byte offsets ----
#define OFF_B0 0         /* hi 32K + lo 32K */
#define OFF_B1 65536
#define OFF_D0 131072    /* [64][136] f32 = 34816 */
#define OFF_D1 165888
#define OFF_Z  200704    /* [64][33] f32 = 8448 */
#define OFF_BB 209152    /* bias slots [2][128] f32 */
#define SMEM_TOTAL 210176

// ---- fragment-linear weight images ----
__device__ uint2 g_WmHi[KK][8][128][32];
__device__ uint2 g_WmLo[KK][8][128][32];
__device__ uint2 g_WgHi[3][128][32];
__device__ uint2 g_WgLo[3][128][32];
__device__ __align__(16) float g_bdre[KK][8][128];
__device__ float g_bdiag[3][128];
// per-CTA diag scratch: [blk][{d1,d2,b}][kj 0..127][sample 0..63]
__device__ float g_dg[NCTA][3][128][64];

__device__ __forceinline__ uint32_t pack2(float a, float b) {
    return (uint32_t)__bfloat16_as_ushort(__float2bfloat16(a)) |
           ((uint32_t)__bfloat16_as_ushort(__float2bfloat16(b)) << 16);
}
__device__ __forceinline__ float bres(float x) {
    return x - __bfloat162float(__float2bfloat16(x));
}

__global__ void prep_kernel(const float* __restrict__ Wd, const float* __restrict__ bd,
                            const float* __restrict__ Wd1, const float* __restrict__ bd1,
                            const float* __restrict__ Wd2, const float* __restrict__ bd2,
                            const float* __restrict__ Wb, const float* __restrict__ bb)
{
    int idx = blockIdx.x * blockDim.x + threadIdx.x;
    if (idx < 131072) {                      // main weights, frag entries
        int lane = idx & 31, slot = (idx >> 5) & 127, c = (idx >> 12) & 7, k = idx >> 15;
        int ks = slot >> 4, nt = slot & 15, g = lane >> 2, t = lane & 3;
        int n = nt * 8 + g, jj = n >> 5, i = n & 31, j = c * 4 + jj;
        const float* src = Wd + (size_t)((i * ZZ + j) * KK + k) * HH + ks * 16 + 2 * t;
        float f0 = src[0], f1 = src[1], f2 = src[8], f3 = src[9];
        g_WmHi[k][c][slot][lane] = make_uint2(pack2(f0, f1), pack2(f2, f3));
        g_WmLo[k][c][slot][lane] = make_uint2(pack2(bres(f0), bres(f1)),
                                              pack2(bres(f2), bres(f3)));
    } else if (idx < 131072 + 12288) {       // diag weights
        int r = idx - 131072;
        int lane = r & 31, slot = (r >> 5) & 127, m = r >> 12;
        int ks = slot >> 4, nt = slot & 15, g = lane >> 2, t = lane & 3;
        int n = nt * 8 + g, kq = n >> 5, j = n & 31;
        const float* W = (m == 0) ? Wd1 : (m == 1) ? Wd2 : Wb;
        const float* src = W + (size_t)(j * KK + kq) * HH + ks * 16 + 2 * t;
        float f0 = src[0], f1 = src[1], f2 = src[8], f3 = src[9];
        g_WgHi[m][slot][lane] = make_uint2(pack2(f0, f1), pack2(f2, f3));
        g_WgLo[m][slot][lane] = make_uint2(pack2(bres(f0), bres(f1)),
                                           pack2(bres(f2), bres(f3)));
    } else if (idx < 131072 + 12288 + 4096) {  // main biases [k][c][n]
        int r = idx - 131072 - 12288;
        int n = r & 127, c = (r >> 7) & 7, k = r >> 10;
        int jj = n >> 5, i = n & 31, j = c * 4 + jj;
        g_bdre[k][c][n] = bd[(i * ZZ + j) * KK + k];
    } else if (idx < 131072 + 12288 + 4096 + 384) {  // diag biases [m][kj]
        int r = idx - 147456;
        int n = r & 127, m = r >> 7;
        int kq = n >> 5, j = n & 31;
        const float* bv = (m == 0) ? bd1 : (m == 1) ? bd2 : bb;
        g_bdiag[m][n] = bv[j * KK + kq];
    }
}

__device__ __forceinline__ void mma_bf16(float c[4], const uint32_t a[4],
                                         uint32_t b0, uint32_t b1) {
    asm volatile(
        "mma.sync.aligned.m16n8k16.row.col.f32.bf16.bf16.f32 "
        "{%0,%1,%2,%3}, {%4,%5,%6,%7}, {%8,%9}, {%0,%1,%2,%3};"
        : "+f"(c[0]), "+f"(c[1]), "+f"(c[2]), "+f"(c[3])
        : "r"(a[0]), "r"(a[1]), "r"(a[2]), "r"(a[3]), "r"(b0), "r"(b1));
}
__device__ __forceinline__ void cp16(uint32_t dst, const void* src) {
    asm volatile("cp.async.cg.shared.global [%0], [%1], 16;" :: "r"(dst), "l"(src));
}
#define CP_COMMIT() asm volatile("cp.async.commit_group;" ::: "memory")
#define CP_WAIT0()  asm volatile("cp.async.wait_group 0;" ::: "memory")

__device__ __forceinline__ uint32_t smem_u32(const void* p) {
    uint32_t a;
    asm("{ .reg .u64 t; cvta.to.shared.u64 t, %1; cvt.u32.u64 %0, t; }" : "=r"(a) : "l"(p));
    return a;
}

// 32x32 warp tile GEMM: reuse each B fragment for both M-tiles.
__device__ __forceinline__ void gemm32(const uint2* __restrict__ Bh,
                                       const uint2* __restrict__ Bl,
                                       int lane, int nq,
                                       const uint32_t aH[2][8][4],
                                       const uint32_t aL[2][8][4],
                                       float acc[2][4][4])
{
    #pragma unroll
    for (int mt = 0; mt < 2; mt++)
        #pragma unroll
        for (int q = 0; q < 4; q++)
            acc[mt][q][0] = acc[mt][q][1] = acc[mt][q][2] = acc[mt][q][3] = 0.f;
    #pragma unroll
    for (int ks = 0; ks < 8; ks++) {
        #pragma unroll
        for (int ntl = 0; ntl < 4; ntl++) {
            int slot = ks * 16 + nq * 4 + ntl;
            uint2 bh = Bh[slot * 32 + lane];
            uint2 bl = Bl[slot * 32 + lane];
            #pragma unroll
            for (int mt = 0; mt < 2; mt++) {
                mma_bf16(acc[mt][ntl], aH[mt][ks], bh.x, bh.y);
                mma_bf16(acc[mt][ntl], aH[mt][ks], bl.x, bl.y);
                mma_bf16(acc[mt][ntl], aL[mt][ks], bh.x, bh.y);
            }
        }
    }
}

// stage main chunk (k2,c2) + bias into buffer `buf` (gemm threads only)
__device__ __forceinline__ void stage_async(uint32_t sb, int buf, int k2, int c2, int tid) {
    const char* sh = (const char*)&g_WmHi[k2][c2][0][0];
    const char* sl = (const char*)&g_WmLo[k2][c2][0][0];
    uint32_t dh = sb + (buf ? OFF_B1 : OFF_B0);
    uint32_t dl = dh + 32768;
    #pragma unroll
    for (int r = 0; r < 8; r++) {
        int i = r * NGT + tid;
        cp16(dh + i * 16, sh + i * 16);
        cp16(dl + i * 16, sl + i * 16);
    }
    if (tid < 32)
        cp16(sb + OFF_BB + buf * 512 + tid * 16,
             (const char*)&g_bdre[k2][c2][0] + tid * 16);
}

__global__ __launch_bounds__(NTH, 1)
void sylv_main(const float* __restrict__ z0, const float* __restrict__ h,
               float* __restrict__ out_z, float* __restrict__ out_ld)
{
    extern __shared__ char sm[];
    const uint32_t sb = smem_u32(sm);
    float* zsm = (float*)(sm + OFF_Z);

    const int tid = threadIdx.x, w = tid >> 5, lane = tid & 31;
    const bool is_g = tid < NGT;
    const int g = lane >> 2, t = lane & 3;
    const int r0 = (w & 1) * 32;            // GEMM row base (32 rows)
    const int nq = w >> 1;                  // GEMM col quarter (32 cols)
    const int cb = nq * 32;
    const int blk = blockIdx.x;
    const int m0 = blk * TM;
    // flow mapping (threads 256..383): f = 0..127, sample ms, half e
    const int f = tid - NGT, ms = f >> 1, e = f & 1;

    const uint2* Bh0 = (const uint2*)(sm + OFF_B0);
    const uint2* Bl0 = (const uint2*)(sm + OFF_B0 + 32768);
    const uint2* Bh1 = (const uint2*)(sm + OFF_B1);
    const uint2* Bl1 = (const uint2*)(sm + OFF_B1 + 32768);

    // ---- A fragments (gemm warps, 2 M-tiles, split bf16 hi/lo) ----
    uint32_t aH[2][8][4], aL[2][8][4];
    if (is_g) {
        const float* hp = h + (size_t)m0 * HH;
        #pragma unroll
        for (int mt = 0; mt < 2; mt++) {
            #pragma unroll
            for (int ks = 0; ks < 8; ks++) {
                int k0 = ks * 16 + 2 * t;
                const float* p0 = hp + (size_t)(r0 + mt * 16 + g) * HH + k0;
                const float* p1 = hp + (size_t)(r0 + mt * 16 + g + 8) * HH + k0;
                float2 x0 = *(const float2*)p0;
                float2 x1 = *(const float2*)p1;
                float2 x2 = *(const float2*)(p0 + 8);
                float2 x3 = *(const float2*)(p1 + 8);
                aH[mt][ks][0] = pack2(x0.x, x0.y); aL[mt][ks][0] = pack2(bres(x0.x), bres(x0.y));
                aH[mt][ks][1] = pack2(x1.x, x1.y); aL[mt][ks][1] = pack2(bres(x1.x), bres(x1.y));
                aH[mt][ks][2] = pack2(x2.x, x2.y); aL[mt][ks][2] = pack2(bres(x2.x), bres(x2.y));
                aH[mt][ks][3] = pack2(x3.x, x3.y); aL[mt][ks][3] = pack2(bres(x3.x), bres(x3.y));
            }
        }
    } else {
        // flow threads load z into smem (16 values each)
        const float* zr = z0 + (size_t)(m0 + ms) * ZZ + e * 16;
        #pragma unroll
        for (int il = 0; il < 16; il++) zsm[ms * 33 + e * 16 + il] = zr[il];
    }

    // ---- diag GEMMs -> global scratch ----
    for (int mm = 0; mm < 3; mm++) {
        if (is_g) {
            const char* sh = (const char*)&g_WgHi[mm][0][0];
            const char* sl = (const char*)&g_WgLo[mm][0][0];
            #pragma unroll
            for (int r = 0; r < 8; r++) {
                int i = r * NGT + tid;
                cp16(sb + OFF_B0 + i * 16, sh + i * 16);
                cp16(sb + OFF_B0 + 32768 + i * 16, sl + i * 16);
            }
            CP_COMMIT(); CP_WAIT0();
        }
        __syncthreads();
        if (is_g) {
            float acc[2][4][4];
            gemm32(Bh0, Bl0, lane, nq, aH, aL, acc);
            #pragma unroll
            for (int mt = 0; mt < 2; mt++) {
                #pragma unroll
                for (int ntl = 0; ntl < 4; ntl++) {
                    int n0 = cb + ntl * 8 + 2 * t;
                    int row = r0 + mt * 16 + g;
                    float b0v = g_bdiag[mm][n0], b1v = g_bdiag[mm][n0 + 1];
                    float v0 = acc[mt][ntl][0] + b0v, v1 = acc[mt][ntl][1] + b1v;
                    float v2 = acc[mt][ntl][2] + b0v, v3 = acc[mt][ntl][3] + b1v;
                    if (mm < 2) { v0 = tanhf(v0); v1 = tanhf(v1); v2 = tanhf(v2); v3 = tanhf(v3); }
                    g_dg[blk][mm][n0][row]         = v0;
                    g_dg[blk][mm][n0 + 1][row]     = v1;
                    g_dg[blk][mm][n0][row + 8]     = v2;
                    g_dg[blk][mm][n0 + 1][row + 8] = v3;
                }
            }
        }
        __syncthreads();
    }

    // ---- prologue: stage B0,B1; GEMM chunk 0 -> D0 ----
    if (is_g) {
        stage_async(sb, 0, 0, 0, tid);
        stage_async(sb, 1, 0, 1, tid);
        CP_COMMIT(); CP_WAIT0();
    }
    __syncthreads();
    if (is_g) {
        float acc[2][4][4];
        gemm32(Bh0, Bl0, lane, nq, aH, aL, acc);
        float* Dd = (float*)(sm + OFF_D0);
        const float* bbp = (const float*)(sm + OFF_BB);
        #pragma unroll
        for (int mt = 0; mt < 2; mt++)
            #pragma unroll
            for (int ntl = 0; ntl < 4; ntl++) {
                int n0 = cb + ntl * 8 + 2 * t;
                int row = r0 + mt * 16 + g;
                float b0v = bbp[n0], b1v = bbp[n0 + 1];
                *(float2*)&Dd[row * DP + n0]       = make_float2(acc[mt][ntl][0] + b0v, acc[mt][ntl][1] + b1v);
                *(float2*)&Dd[(row + 8) * DP + n0] = make_float2(acc[mt][ntl][2] + b0v, acc[mt][ntl][3] + b1v);
            }
    }
    __syncthreads();

    // ---- main loop: GEMM warps compute chunk cc+1; flow warps consume chunk cc ----
    float zp[16], dz[16], ld_acc = 0.f;

    #pragma unroll 1
    for (int cc = 0; cc < 32; cc++) {
        const int k = cc >> 3, c = cc & 7, flip = k & 1;
        const int nx = cc + 1;
        const int jbase = c * 4;

        if (is_g) {
            if (cc <= 29) stage_async(sb, cc & 1, (cc + 2) >> 3, (cc + 2) & 7, tid);
            if (nx < 32) {
                float acc[2][4][4];
                gemm32((nx & 1) ? Bh1 : Bh0, (nx & 1) ? Bl1 : Bl0, lane, nq, aH, aL, acc);
                float* Dd = (float*)(sm + ((nx & 1) ? OFF_D1 : OFF_D0));
                const float* bbp = (const float*)(sm + OFF_BB + (nx & 1) * 512);
                #pragma unroll
                for (int mt = 0; mt < 2; mt++)
                    #pragma unroll
                    for (int ntl = 0; ntl < 4; ntl++) {
                        int n0 = cb + ntl * 8 + 2 * t;
                        int row = r0 + mt * 16 + g;
                        float b0v = bbp[n0], b1v = bbp[n0 + 1];
                        *(float2*)&Dd[row * DP + n0]       = make_float2(acc[mt][ntl][0] + b0v, acc[mt][ntl][1] + b1v);
                        *(float2*)&Dd[(row + 8) * DP + n0] = make_float2(acc[mt][ntl][2] + b0v, acc[mt][ntl][3] + b1v);
                    }
            }
            CP_COMMIT(); CP_WAIT0();
        } else {
            // ---- flow chunk cc (thread = (ms, e), i-range e*16..e*16+15) ----
            const float* Dc = (const float*)(sm + ((cc & 1) ? OFF_D1 : OFF_D0));
            const int j0 = jbase + 2 * e;     // owned j's: j0, j0+1
            // diag/bias prefetch (L2-resident)
            float d2o0 = g_dg[blk][1][k * 32 + j0][ms];
            float d2o1 = g_dg[blk][1][k * 32 + j0 + 1][ms];
            float bo0  = g_dg[blk][2][k * 32 + j0][ms];
            float bo1  = g_dg[blk][2][k * 32 + j0 + 1][ms];
            float d1a[4];
            #pragma unroll
            for (int jj = 0; jj < 4; jj++)
                d1a[jj] = g_dg[blk][0][k * 32 + jbase + jj][ms];
            float zpj0 = zsm[ms * 33 + (flip ? 31 - j0 : j0)];
            float zpj1 = zsm[ms * 33 + (flip ? 31 - (j0 + 1) : (j0 + 1))];

            if (c == 0) {
                #pragma unroll
                for (int il = 0; il < 16; il++) {
                    int gi = e * 16 + il;
                    zp[il] = zsm[ms * 33 + (flip ? 31 - gi : gi)];
                    dz[il] = 0.f;
                }
            }
            float Dv[4][16];
            #pragma unroll
            for (int jj = 0; jj < 4; jj++) {
                const float4* p = (const float4*)&Dc[ms * DP + jj * 32 + e * 16];
                float4 x0 = p[0], x1 = p[1], x2 = p[2], x3 = p[3];
                Dv[jj][0] = x0.x;  Dv[jj][1] = x0.y;  Dv[jj][2] = x0.z;  Dv[jj][3] = x0.w;
                Dv[jj][4] = x1.x;  Dv[jj][5] = x1.y;  Dv[jj][6] = x1.z;  Dv[jj][7] = x1.w;
                Dv[jj][8] = x2.x;  Dv[jj][9] = x2.y;  Dv[jj][10] = x2.z; Dv[jj][11] = x2.w;
                Dv[jj][12] = x3.x; Dv[jj][13] = x3.y; Dv[jj][14] = x3.z; Dv[jj][15] = x3.w;
            }
            float part[4];
            #pragma unroll
            for (int jj = 0; jj < 4; jj++) {
                int j = jbase + jj;
                float s = 0.f;
                #pragma unroll
                for (int il = 0; il < 16; il++) {
                    int gi = e * 16 + il;
                    s = fmaf(zp[il], (gi > j) ? Dv[jj][il] : 0.f, s);
                }
                part[jj] = s;
            }
            #pragma unroll
            for (int jj = 0; jj < 4; jj++)
                part[jj] += __shfl_xor_sync(0xffffffffu, part[jj], 1);
            float pa = e ? part[2] : part[0];
            float pb = e ? part[3] : part[1];
            float t0 = tanhf(pa + bo0 + zpj0 * d2o0);
            float t1 = tanhf(pb + bo1 + zpj1 * d2o1);
            float d1o0 = e ? d1a[2] : d1a[0];
            float d1o1 = e ? d1a[3] : d1a[1];
            ld_acc += logf(fabsf(fmaf(1.f - t0 * t0, d1o0 * d2o0, 1.f)));
            ld_acc += logf(fabsf(fmaf(1.f - t1 * t1, d1o1 * d2o1, 1.f)));
            float u0 = __shfl_xor_sync(0xffffffffu, t0, 1);
            float u1 = __shfl_xor_sync(0xffffffffu, t1, 1);
            float tj[4];
            tj[0] = e ? u0 : t0;  tj[1] = e ? u1 : t1;
            tj[2] = e ? t0 : u0;  tj[3] = e ? t1 : u1;
            #pragma unroll
            for (int jj = 0; jj < 4; jj++) {
                int j = jbase + jj;
                #pragma unroll
                for (int il = 0; il < 16; il++) {
                    int gi = e * 16 + il;
                    float coef = (gi < j) ? Dv[jj][il] : ((gi == j) ? d1a[jj] : 0.f);
                    dz[il] = fmaf(tj[jj], coef, dz[il]);
                }
            }
            if (c == 7) {
                #pragma unroll
                for (int il = 0; il < 16; il++) {
                    int gi = e * 16 + il;
                    zsm[ms * 33 + (flip ? 31 - gi : gi)] += dz[il];
                }
            }
        }
        __syncthreads();
    }

    // ---- outputs (flow threads) ----
    if (!is_g) {
        float v = ld_acc + __shfl_xor_sync(0xffffffffu, ld_acc, 1);
        if (e == 0) out_ld[m0 + ms] = v;
        float* oz = out_z + (size_t)(m0 + ms) * ZZ + e * 16;
        #pragma unroll
        for (int il = 0; il < 16; il++) oz[il] = zsm[ms * 33 + e * 16 + il];
    }
}

extern "C" void kernel_launch(void* const* d_in, const int* in_sizes, int n_in,
                              void* d_out, int out_size)
{
    const float* z0  = (const float*)d_in[0];
    const float* h   = (const float*)d_in[1];
    const float* Wd  = (const float*)d_in[2];
    const float* bd  = (const float*)d_in[3];
    const float* Wd1 = (const float*)d_in[4];
    const float* bd1 = (const float*)d_in[5];
    const float* Wd2 = (const float*)d_in[6];
    const float* bd2 = (const float*)d_in[7];
    const float* Wb  = (const float*)d_in[8];
    const float* bb  = (const float*)d_in[9];

    const int B = in_sizes[0] / ZZ;          // 32768
    float* out_z  = (float*)d_out;
    float* out_ld = (float*)d_out + (size_t)B * ZZ;

    int prep_elems = 131072 + 12288 + 4096 + 384;
    prep_kernel<<<(prep_elems + 255) / 256, 256>>>(Wd, bd, Wd1, bd1, Wd2, bd2, Wb, bb);

    cudaFuncSetAttribute(sylv_main, cudaFuncAttributeMaxDynamicSharedMemorySize, SMEM_TOTAL);
    sylv_main<<<B / TM, NTH, SMEM_TOTAL>>>(z0, h, out_z, out_ld);
}

// round 10
// speedup vs baseline: 1.3203x; 1.3203x over previous
#include <cuda_runtime.h>
#include <cuda_bf16.h>
#include <stdint.h>
#include <math.h>

// TriangularSylvesterNeRF  Z=32 K=4 H=128 B=32768
// mma.sync bf16 split-precision, monolithic pipeline (round-6 structure)
// + quad-interleaved MMA ordering (break RAW chains)
// + uint4-interleaved B fragments (1 LDS.128 per slot)
// + diag prefetch one chunk ahead.

#define ZZ 32
#define KK 4
#define HH 128
#define TM 64
#define NTH 256
#define NCTA 512
#define DP 132          /* D row pitch (floats): conflict-free 4-thread reads */

// ---- smem byte offsets ----
#define OFF_B0 0        /* interleaved hi/lo, 64KB */
#define OFF_B1 65536
#define OFF_D0 131072   /* [64][132] f32 = 33792 */
#define OFF_D1 164864
#define OFF_Z  198656   /* [64][33] f32 = 8448 */
#define OFF_BB 207104   /* bias slots [2][128] f32 */
#define SMEM_TOTAL 208128

// ---- fragment-linear weight images, interleaved {hi.x,hi.y,lo.x,lo.y} ----
__device__ uint4 g_Wm[KK][8][128][32];
__device__ uint4 g_Wg[3][128][32];
__device__ __align__(16) float g_bdre[KK][8][128];
__device__ float g_bdiag[3][128];
// per-CTA diag scratch: [blk][{d1,d2,b}][kj 0..127][sample 0..63]
__device__ float g_dg[NCTA][3][128][64];

__device__ __forceinline__ uint32_t pack2(float a, float b) {
    return (uint32_t)__bfloat16_as_ushort(__float2bfloat16(a)) |
           ((uint32_t)__bfloat16_as_ushort(__float2bfloat16(b)) << 16);
}
__device__ __forceinline__ float bres(float x) {
    return x - __bfloat162float(__float2bfloat16(x));
}

__global__ void prep_kernel(const float* __restrict__ Wd, const float* __restrict__ bd,
                            const float* __restrict__ Wd1, const float* __restrict__ bd1,
                            const float* __restrict__ Wd2, const float* __restrict__ bd2,
                            const float* __restrict__ Wb, const float* __restrict__ bb)
{
    int idx = blockIdx.x * blockDim.x + threadIdx.x;
    if (idx < 131072) {                      // main weights, frag entries
        int lane = idx & 31, slot = (idx >> 5) & 127, c = (idx >> 12) & 7, k = idx >> 15;
        int ks = slot >> 4, nt = slot & 15, g = lane >> 2, t = lane & 3;
        int n = nt * 8 + g, jj = n >> 5, i = n & 31, j = c * 4 + jj;
        const float* src = Wd + (size_t)((i * ZZ + j) * KK + k) * HH + ks * 16 + 2 * t;
        float f0 = src[0], f1 = src[1], f2 = src[8], f3 = src[9];
        g_Wm[k][c][slot][lane] = make_uint4(pack2(f0, f1), pack2(f2, f3),
                                            pack2(bres(f0), bres(f1)),
                                            pack2(bres(f2), bres(f3)));
    } else if (idx < 131072 + 12288) {       // diag weights
        int r = idx - 131072;
        int lane = r & 31, slot = (r >> 5) & 127, m = r >> 12;
        int ks = slot >> 4, nt = slot & 15, g = lane >> 2, t = lane & 3;
        int n = nt * 8 + g, kq = n >> 5, j = n & 31;
        const float* W = (m == 0) ? Wd1 : (m == 1) ? Wd2 : Wb;
        const float* src = W + (size_t)(j * KK + kq) * HH + ks * 16 + 2 * t;
        float f0 = src[0], f1 = src[1], f2 = src[8], f3 = src[9];
        g_Wg[m][slot][lane] = make_uint4(pack2(f0, f1), pack2(f2, f3),
                                         pack2(bres(f0), bres(f1)),
                                         pack2(bres(f2), bres(f3)));
    } else if (idx < 131072 + 12288 + 4096) {  // main biases [k][c][n]
        int r = idx - 131072 - 12288;
        int n = r & 127, c = (r >> 7) & 7, k = r >> 10;
        int jj = n >> 5, i = n & 31, j = c * 4 + jj;
        g_bdre[k][c][n] = bd[(i * ZZ + j) * KK + k];
    } else if (idx < 131072 + 12288 + 4096 + 384) {  // diag biases [m][kj]
        int r = idx - 147456;
        int n = r & 127, m = r >> 7;
        int kq = n >> 5, j = n & 31;
        const float* bv = (m == 0) ? bd1 : (m == 1) ? bd2 : bb;
        g_bdiag[m][n] = bv[j * KK + kq];
    }
}

__device__ __forceinline__ void mma_bf16(float c[4], const uint32_t a[4],
                                         uint32_t b0, uint32_t b1) {
    asm volatile(
        "mma.sync.aligned.m16n8k16.row.col.f32.bf16.bf16.f32 "
        "{%0,%1,%2,%3}, {%4,%5,%6,%7}, {%8,%9}, {%0,%1,%2,%3};"
        : "+f"(c[0]), "+f"(c[1]), "+f"(c[2]), "+f"(c[3])
        : "r"(a[0]), "r"(a[1]), "r"(a[2]), "r"(a[3]), "r"(b0), "r"(b1));
}
__device__ __forceinline__ void cp16(uint32_t dst, const void* src) {
    asm volatile("cp.async.cg.shared.global [%0], [%1], 16;" :: "r"(dst), "l"(src));
}
#define CP_COMMIT() asm volatile("cp.async.commit_group;" ::: "memory")
#define CP_WAIT0()  asm volatile("cp.async.wait_group 0;" ::: "memory")

__device__ __forceinline__ uint32_t smem_u32(const void* p) {
    uint32_t a;
    asm("{ .reg .u64 t; cvta.to.shared.u64 t, %1; cvt.u32.u64 %0, t; }" : "=r"(a) : "l"(p));
    return a;
}

// GEMM chunk: 16x64 warp tile, quad-interleaved product-major MMA order.
__device__ __forceinline__ void gemm_chunk(const uint4* __restrict__ Bq,
                                           int lane, int nt0,
                                           const uint32_t aH[8][4],
                                           const uint32_t aL[8][4],
                                           float acc[8][4])
{
    #pragma unroll
    for (int q = 0; q < 8; q++)
        acc[q][0] = acc[q][1] = acc[q][2] = acc[q][3] = 0.f;
    #pragma unroll
    for (int ks = 0; ks < 8; ks++) {
        #pragma unroll
        for (int half = 0; half < 2; half++) {
            const int base = ks * 16 + nt0 + half * 4;
            uint4 b0 = Bq[(base + 0) * 32 + lane];
            uint4 b1 = Bq[(base + 1) * 32 + lane];
            uint4 b2 = Bq[(base + 2) * 32 + lane];
            uint4 b3 = Bq[(base + 3) * 32 + lane];
            float* a0 = acc[half * 4 + 0];
            float* a1 = acc[half * 4 + 1];
            float* a2 = acc[half * 4 + 2];
            float* a3 = acc[half * 4 + 3];
            // product 1: aH * bH   (RAW distance 4)
            mma_bf16(a0, aH[ks], b0.x, b0.y);
            mma_bf16(a1, aH[ks], b1.x, b1.y);
            mma_bf16(a2, aH[ks], b2.x, b2.y);
            mma_bf16(a3, aH[ks], b3.x, b3.y);
            // product 2: aH * bL
            mma_bf16(a0, aH[ks], b0.z, b0.w);
            mma_bf16(a1, aH[ks], b1.z, b1.w);
            mma_bf16(a2, aH[ks], b2.z, b2.w);
            mma_bf16(a3, aH[ks], b3.z, b3.w);
            // product 3: aL * bH
            mma_bf16(a0, aL[ks], b0.x, b0.y);
            mma_bf16(a1, aL[ks], b1.x, b1.y);
            mma_bf16(a2, aL[ks], b2.x, b2.y);
            mma_bf16(a3, aL[ks], b3.x, b3.y);
        }
    }
}

// stage main chunk (k2,c2) + its bias into buffer `buf` (async)
__device__ __forceinline__ void stage_async(uint32_t sb, int buf, int k2, int c2, int tid) {
    const char* s = (const char*)&g_Wm[k2][c2][0][0];
    uint32_t d = sb + (buf ? OFF_B1 : OFF_B0);
    #pragma unroll
    for (int r = 0; r < 16; r++) {
        int i = r * NTH + tid;
        cp16(d + i * 16, s + i * 16);
    }
    if (tid < 32)
        cp16(sb + OFF_BB + buf * 512 + tid * 16,
             (const char*)&g_bdre[k2][c2][0] + tid * 16);
}

__global__ __launch_bounds__(NTH, 1)
void sylv_main(const float* __restrict__ z0, const float* __restrict__ h,
               float* __restrict__ out_z, float* __restrict__ out_ld)
{
    extern __shared__ char sm[];
    const uint32_t sb = smem_u32(sm);
    float* zsm = (float*)(sm + OFF_Z);

    const int tid = threadIdx.x, w = tid >> 5, lane = tid & 31;
    const int g = lane >> 2, t = lane & 3;
    const int r0  = (w & 3) * 16;          // GEMM row base
    const int nt0 = (w >> 2) * 8;          // GEMM ntile base
    const int cb  = nt0 * 8;               // GEMM col base
    const int blk = blockIdx.x;
    const int m0  = blk * TM;
    const int msamp = tid >> 2, q = tid & 3;   // flow: sample / quarter

    // ---- A fragments (persist): split bf16 hi/lo ----
    uint32_t aH[8][4], aL[8][4];
    {
        const float* hp = h + (size_t)m0 * HH;
        #pragma unroll
        for (int ks = 0; ks < 8; ks++) {
            int k0 = ks * 16 + 2 * t;
            const float* p0 = hp + (size_t)(r0 + g) * HH + k0;
            const float* p1 = hp + (size_t)(r0 + g + 8) * HH + k0;
            float2 x0 = *(const float2*)p0;
            float2 x1 = *(const float2*)p1;
            float2 x2 = *(const float2*)(p0 + 8);
            float2 x3 = *(const float2*)(p1 + 8);
            aH[ks][0] = pack2(x0.x, x0.y); aL[ks][0] = pack2(bres(x0.x), bres(x0.y));
            aH[ks][1] = pack2(x1.x, x1.y); aL[ks][1] = pack2(bres(x1.x), bres(x1.y));
            aH[ks][2] = pack2(x2.x, x2.y); aL[ks][2] = pack2(bres(x2.x), bres(x2.y));
            aH[ks][3] = pack2(x3.x, x3.y); aL[ks][3] = pack2(bres(x3.x), bres(x3.y));
        }
    }
    // ---- z into smem ----
    for (int idx = tid; idx < TM * ZZ; idx += NTH)
        zsm[(idx >> 5) * 33 + (idx & 31)] = z0[(size_t)(m0 + (idx >> 5)) * ZZ + (idx & 31)];

    const uint4* Bq0 = (const uint4*)(sm + OFF_B0);
    const uint4* Bq1 = (const uint4*)(sm + OFF_B1);

    // ---- diag GEMMs -> global scratch ----
    for (int mm = 0; mm < 3; mm++) {
        {
            const char* s = (const char*)&g_Wg[mm][0][0];
            #pragma unroll
            for (int r = 0; r < 16; r++) {
                int i = r * NTH + tid;
                cp16(sb + OFF_B0 + i * 16, s + i * 16);
            }
        }
        CP_COMMIT(); CP_WAIT0();
        __syncthreads();
        float acc[8][4];
        gemm_chunk(Bq0, lane, nt0, aH, aL, acc);
        #pragma unroll
        for (int ntl = 0; ntl < 8; ntl++) {
            int n0 = cb + ntl * 8 + 2 * t;
            float b0v = g_bdiag[mm][n0], b1v = g_bdiag[mm][n0 + 1];
            float v0 = acc[ntl][0] + b0v, v1 = acc[ntl][1] + b1v;
            float v2 = acc[ntl][2] + b0v, v3 = acc[ntl][3] + b1v;
            if (mm < 2) { v0 = tanhf(v0); v1 = tanhf(v1); v2 = tanhf(v2); v3 = tanhf(v3); }
            g_dg[blk][mm][n0][r0 + g]         = v0;
            g_dg[blk][mm][n0 + 1][r0 + g]     = v1;
            g_dg[blk][mm][n0][r0 + g + 8]     = v2;
            g_dg[blk][mm][n0 + 1][r0 + g + 8] = v3;
        }
        __syncthreads();
    }

    // ---- stage B0,B1; GEMM chunk 0 -> D0 ----
    stage_async(sb, 0, 0, 0, tid);
    stage_async(sb, 1, 0, 1, tid);
    CP_COMMIT(); CP_WAIT0();
    __syncthreads();
    {
        float acc[8][4];
        gemm_chunk(Bq0, lane, nt0, aH, aL, acc);
        float* Dd = (float*)(sm + OFF_D0);
        const float* bbp = (const float*)(sm + OFF_BB);
        #pragma unroll
        for (int ntl = 0; ntl < 8; ntl++) {
            int n0 = cb + ntl * 8 + 2 * t;
            float b0v = bbp[n0], b1v = bbp[n0 + 1];
            *(float2*)&Dd[(r0 + g) * DP + n0]     = make_float2(acc[ntl][0] + b0v, acc[ntl][1] + b1v);
            *(float2*)&Dd[(r0 + g + 8) * DP + n0] = make_float2(acc[ntl][2] + b0v, acc[ntl][3] + b1v);
        }
    }
    __syncthreads();

    // ---- diag prefetch for chunk 0 ----
    float pf_d2, pf_b, pf_d1[4];
    {
        pf_d2 = g_dg[blk][1][q][msamp];
        pf_b  = g_dg[blk][2][q][msamp];
        #pragma unroll
        for (int jj = 0; jj < 4; jj++) pf_d1[jj] = g_dg[blk][0][jj][msamp];
    }

    // ---- main pipelined loop ----
    float zp[8], dz[8], ld_acc = 0.f;

    #pragma unroll 1
    for (int cc = 0; cc < 32; cc++) {
        const int k = cc >> 3, c = cc & 7, flip = k & 1;
        const int nx = cc + 1;
        const int jbase = c * 4;

        // consume prefetched diag values; issue prefetch for chunk cc+1
        float d2m = pf_d2, bm = pf_b;
        float d1a[4];
        #pragma unroll
        for (int jj = 0; jj < 4; jj++) d1a[jj] = pf_d1[jj];
        if (nx < 32) {
            const int k2 = nx >> 3, jb2 = (nx & 7) * 4;
            pf_d2 = g_dg[blk][1][k2 * 32 + jb2 + q][msamp];
            pf_b  = g_dg[blk][2][k2 * 32 + jb2 + q][msamp];
            #pragma unroll
            for (int jj = 0; jj < 4; jj++)
                pf_d1[jj] = g_dg[blk][0][k2 * 32 + jb2 + jj][msamp];
        }

        // stage chunk cc+2 under the MMAs
        if (cc <= 29) stage_async(sb, cc & 1, (cc + 2) >> 3, (cc + 2) & 7, tid);

        // GEMM chunk nx (tensor pipe)
        float acc[8][4];
        if (nx < 32)
            gemm_chunk((nx & 1) ? Bq1 : Bq0, lane, nt0, aH, aL, acc);

        // ---- flow chunk cc (fma pipe, overlaps MMA drain) ----
        {
            const float* Dc = (const float*)(sm + ((cc & 1) ? OFF_D1 : OFF_D0));
            if (c == 0) {
                #pragma unroll
                for (int il = 0; il < 8; il++) {
                    int gi = q * 8 + il;
                    zp[il] = zsm[msamp * 33 + (flip ? 31 - gi : gi)];
                    dz[il] = 0.f;
                }
            }
            float zpj = zsm[msamp * 33 + (flip ? 31 - (jbase + q) : (jbase + q))];

            float Dv[4][8];
            #pragma unroll
            for (int jj = 0; jj < 4; jj++) {
                const float4* p = (const float4*)&Dc[msamp * DP + jj * 32 + q * 8];
                float4 x = p[0], y = p[1];
                Dv[jj][0] = x.x; Dv[jj][1] = x.y; Dv[jj][2] = x.z; Dv[jj][3] = x.w;
                Dv[jj][4] = y.x; Dv[jj][5] = y.y; Dv[jj][6] = y.z; Dv[jj][7] = y.w;
            }
            float part[4];
            #pragma unroll
            for (int jj = 0; jj < 4; jj++) {
                int j = jbase + jj;
                float s = 0.f;
                #pragma unroll
                for (int il = 0; il < 8; il++) {
                    int gi = q * 8 + il;
                    s = fmaf(zp[il], (gi > j) ? Dv[jj][il] : 0.f, s);
                }
                part[jj] = s;
            }
            #pragma unroll
            for (int jj = 0; jj < 4; jj++) {
                part[jj] += __shfl_xor_sync(0xffffffffu, part[jj], 1);
                part[jj] += __shfl_xor_sync(0xffffffffu, part[jj], 2);
            }
            float prem = (q == 0) ? part[0] : (q == 1) ? part[1]
                       : (q == 2) ? part[2] : part[3];
            float d1m  = (q == 0) ? d1a[0] : (q == 1) ? d1a[1]
                       : (q == 2) ? d1a[2] : d1a[3];
            prem += bm + zpj * d2m;
            float tm = tanhf(prem);
            ld_acc += logf(fabsf(fmaf(1.f - tm * tm, d1m * d2m, 1.f)));
            float ta = __shfl_xor_sync(0xffffffffu, tm, 1);
            float tb = __shfl_xor_sync(0xffffffffu, tm, 2);
            float tc = __shfl_xor_sync(0xffffffffu, ta, 2);
            #pragma unroll
            for (int jj = 0; jj < 4; jj++) {
                int j = jbase + jj, sel = jj ^ q;
                float tj = (sel == 0) ? tm : (sel == 1) ? ta : (sel == 2) ? tb : tc;
                #pragma unroll
                for (int il = 0; il < 8; il++) {
                    int gi = q * 8 + il;
                    float coef = (gi < j) ? Dv[jj][il] : ((gi == j) ? d1a[jj] : 0.f);
                    dz[il] = fmaf(tj, coef, dz[il]);
                }
            }
            if (c == 7) {
                #pragma unroll
                for (int il = 0; il < 8; il++) {
                    int gi = q * 8 + il;
                    zsm[msamp * 33 + (flip ? 31 - gi : gi)] += dz[il];
                }
            }
        }

        // store GEMM result for chunk nx
        if (nx < 32) {
            float* Dd = (float*)(sm + ((nx & 1) ? OFF_D1 : OFF_D0));
            const float* bbp = (const float*)(sm + OFF_BB + (nx & 1) * 512);
            #pragma unroll
            for (int ntl = 0; ntl < 8; ntl++) {
                int n0 = cb + ntl * 8 + 2 * t;
                float b0v = bbp[n0], b1v = bbp[n0 + 1];
                *(float2*)&Dd[(r0 + g) * DP + n0]     = make_float2(acc[ntl][0] + b0v, acc[ntl][1] + b1v);
                *(float2*)&Dd[(r0 + g + 8) * DP + n0] = make_float2(acc[ntl][2] + b0v, acc[ntl][3] + b1v);
            }
        }
        CP_COMMIT(); CP_WAIT0();
        __syncthreads();
    }

    // ---- outputs ----
    float v = ld_acc;
    v += __shfl_xor_sync(0xffffffffu, v, 1);
    v += __shfl_xor_sync(0xffffffffu, v, 2);
    if (q == 0) out_ld[m0 + msamp] = v;
    for (int idx = tid; idx < TM * ZZ; idx += NTH)
        out_z[(size_t)(m0 + (idx >> 5)) * ZZ + (idx & 31)] = zsm[(idx >> 5) * 33 + (idx & 31)];
}

extern "C" void kernel_launch(void* const* d_in, const int* in_sizes, int n_in,
                              void* d_out, int out_size)
{
    const float* z0  = (const float*)d_in[0];
    const float* h   = (const float*)d_in[1];
    const float* Wd  = (const float*)d_in[2];
    const float* bd  = (const float*)d_in[3];
    const float* Wd1 = (const float*)d_in[4];
    const float* bd1 = (const float*)d_in[5];
    const float* Wd2 = (const float*)d_in[6];
    const float* bd2 = (const float*)d_in[7];
    const float* Wb  = (const float*)d_in[8];
    const float* bb  = (const float*)d_in[9];

    const int B = in_sizes[0] / ZZ;          // 32768
    float* out_z  = (float*)d_out;
    float* out_ld = (float*)d_out + (size_t)B * ZZ;

    int prep_elems = 131072 + 12288 + 4096 + 384;
    prep_kernel<<<(prep_elems + 255) / 256, 256>>>(Wd, bd, Wd1, bd1, Wd2, bd2, Wb, bb);

    cudaFuncSetAttribute(sylv_main, cudaFuncAttributeMaxDynamicSharedMemorySize, SMEM_TOTAL);
    sylv_main<<<B / TM, NTH, SMEM_TOTAL>>>(z0, h, out_z, out_ld);
}

// round 11
// speedup vs baseline: 1.6935x; 1.2827x over previous
#include <cuda_runtime.h>
#include <cuda_bf16.h>
#include <stdint.h>
#include <math.h>

// TriangularSylvesterNeRF  Z=32 K=4 H=128 B=32768
// mma.sync bf16 split-precision; 64-col half-chunks; 2 CTAs/SM (smem 107KB, regs<=128).

#define ZZ 32
#define KK 4
#define HH 128
#define TM 64
#define NTH 256
#define NCTA 512
#define DP 68            /* D row pitch (floats) */

// ---- smem byte offsets ----
#define OFF_B0 0         /* 32KB interleaved hi/lo */
#define OFF_B1 32768
#define OFF_D0 65536     /* [64][68] f32 = 17408 */
#define OFF_D1 82944
#define OFF_Z  100352    /* [64][33] f32 = 8448 */
#define OFF_BB 108800    /* bias slots [2][64] f32 */
#define SMEM_TOTAL 109312

// ---- fragment-linear weight images, interleaved {hi.x,hi.y,lo.x,lo.y} ----
// main: [k][half-chunk hc 0..15][slot = ks*8+ntl][lane]; cols n = hc*64 + ntl*8 + g,
// global n-ordering n = j*32 + i  (j = n>>5, i = n&31)
__device__ uint4 g_Wm[KK][16][64][32];
__device__ uint4 g_Wg[3][2][64][32];
__device__ __align__(16) float g_bdre[KK][16][64];
__device__ float g_bdiag[3][128];
// per-CTA diag scratch: [blk][{d1,d2,b}][kj 0..127][sample 0..63]
__device__ float g_dg[NCTA][3][128][64];

__device__ __forceinline__ uint32_t pack2(float a, float b) {
    return (uint32_t)__bfloat16_as_ushort(__float2bfloat16(a)) |
           ((uint32_t)__bfloat16_as_ushort(__float2bfloat16(b)) << 16);
}
__device__ __forceinline__ float bres(float x) {
    return x - __bfloat162float(__float2bfloat16(x));
}

__global__ void prep_kernel(const float* __restrict__ Wd, const float* __restrict__ bd,
                            const float* __restrict__ Wd1, const float* __restrict__ bd1,
                            const float* __restrict__ Wd2, const float* __restrict__ bd2,
                            const float* __restrict__ Wb, const float* __restrict__ bb)
{
    int idx = blockIdx.x * blockDim.x + threadIdx.x;
    if (idx < 131072) {                      // main weights
        int lane = idx & 31, slot = (idx >> 5) & 63, hc = (idx >> 11) & 15, k = idx >> 15;
        int ks = slot >> 3, ntl = slot & 7, g = lane >> 2, t = lane & 3;
        int n = hc * 64 + ntl * 8 + g;
        int j = n >> 5, i = n & 31;
        const float* src = Wd + (size_t)((i * ZZ + j) * KK + k) * HH + ks * 16 + 2 * t;
        float f0 = src[0], f1 = src[1], f2 = src[8], f3 = src[9];
        g_Wm[k][hc][slot][lane] = make_uint4(pack2(f0, f1), pack2(f2, f3),
                                             pack2(bres(f0), bres(f1)),
                                             pack2(bres(f2), bres(f3)));
    } else if (idx < 131072 + 12288) {       // diag weights
        int r = idx - 131072;
        int lane = r & 31, slot = (r >> 5) & 63, half = (r >> 11) & 1, m = r >> 12;
        int ks = slot >> 3, ntl = slot & 7, g = lane >> 2, t = lane & 3;
        int n = half * 64 + ntl * 8 + g;     // n = kq*32 + j
        int kq = n >> 5, j = n & 31;
        const float* W = (m == 0) ? Wd1 : (m == 1) ? Wd2 : Wb;
        const float* src = W + (size_t)(j * KK + kq) * HH + ks * 16 + 2 * t;
        float f0 = src[0], f1 = src[1], f2 = src[8], f3 = src[9];
        g_Wg[m][half][slot][lane] = make_uint4(pack2(f0, f1), pack2(f2, f3),
                                               pack2(bres(f0), bres(f1)),
                                               pack2(bres(f2), bres(f3)));
    } else if (idx < 131072 + 12288 + 4096) {  // main biases [k][hc][64]
        int r = idx - 131072 - 12288;
        int l = r & 63, hc = (r >> 6) & 15, k = r >> 10;
        int n = hc * 64 + l;
        int j = n >> 5, i = n & 31;
        g_bdre[k][hc][l] = bd[(i * ZZ + j) * KK + k];
    } else if (idx < 131072 + 12288 + 4096 + 384) {  // diag biases [m][kj]
        int r = idx - 147456;
        int n = r & 127, m = r >> 7;
        int kq = n >> 5, j = n & 31;
        const float* bv = (m == 0) ? bd1 : (m == 1) ? bd2 : bb;
        g_bdiag[m][n] = bv[j * KK + kq];
    }
}

__device__ __forceinline__ void mma_bf16(float c[4], const uint32_t a[4],
                                         uint32_t b0, uint32_t b1) {
    asm volatile(
        "mma.sync.aligned.m16n8k16.row.col.f32.bf16.bf16.f32 "
        "{%0,%1,%2,%3}, {%4,%5,%6,%7}, {%8,%9}, {%0,%1,%2,%3};"
        : "+f"(c[0]), "+f"(c[1]), "+f"(c[2]), "+f"(c[3])
        : "r"(a[0]), "r"(a[1]), "r"(a[2]), "r"(a[3]), "r"(b0), "r"(b1));
}
__device__ __forceinline__ void cp16(uint32_t dst, const void* src) {
    asm volatile("cp.async.cg.shared.global [%0], [%1], 16;" :: "r"(dst), "l"(src));
}
#define CP_COMMIT() asm volatile("cp.async.commit_group;" ::: "memory")
#define CP_WAIT0()  asm volatile("cp.async.wait_group 0;" ::: "memory")
#define CP_WAIT1()  asm volatile("cp.async.wait_group 1;" ::: "memory")

__device__ __forceinline__ uint32_t smem_u32(const void* p) {
    uint32_t a;
    asm("{ .reg .u64 t; cvta.to.shared.u64 t, %1; cvt.u32.u64 %0, t; }" : "=r"(a) : "l"(p));
    return a;
}

// Half-chunk GEMM: warp tile 16 rows x 32 cols, quad-interleaved MMA order.
__device__ __forceinline__ void gemm_h(const uint4* __restrict__ Bq,
                                       int lane, int nq,
                                       const uint32_t aH[8][4],
                                       const uint32_t aL[8][4],
                                       float acc[4][4])
{
    #pragma unroll
    for (int q = 0; q < 4; q++)
        acc[q][0] = acc[q][1] = acc[q][2] = acc[q][3] = 0.f;
    #pragma unroll
    for (int ks = 0; ks < 8; ks++) {
        const int base = ks * 8 + nq * 4;
        uint4 b0 = Bq[(base + 0) * 32 + lane];
        uint4 b1 = Bq[(base + 1) * 32 + lane];
        uint4 b2 = Bq[(base + 2) * 32 + lane];
        uint4 b3 = Bq[(base + 3) * 32 + lane];
        mma_bf16(acc[0], aH[ks], b0.x, b0.y);
        mma_bf16(acc[1], aH[ks], b1.x, b1.y);
        mma_bf16(acc[2], aH[ks], b2.x, b2.y);
        mma_bf16(acc[3], aH[ks], b3.x, b3.y);
        mma_bf16(acc[0], aH[ks], b0.z, b0.w);
        mma_bf16(acc[1], aH[ks], b1.z, b1.w);
        mma_bf16(acc[2], aH[ks], b2.z, b2.w);
        mma_bf16(acc[3], aH[ks], b3.z, b3.w);
        mma_bf16(acc[0], aL[ks], b0.x, b0.y);
        mma_bf16(acc[1], aL[ks], b1.x, b1.y);
        mma_bf16(acc[2], aL[ks], b2.x, b2.y);
        mma_bf16(acc[3], aL[ks], b3.x, b3.y);
    }
}

// stage 32KB (2048 uint4) to smem buffer
__device__ __forceinline__ void stage32k(uint32_t dst, const void* srcv, int tid) {
    const char* s = (const char*)srcv;
    #pragma unroll
    for (int r = 0; r < 8; r++) {
        int i = r * NTH + tid;
        cp16(dst + i * 16, s + i * 16);
    }
}
// stage main half-chunk hcg (0..63) + its bias into buffer `buf`
__device__ __forceinline__ void stage_main(uint32_t sb, int buf, int hcg, int tid) {
    int k2 = hcg >> 4, hc = hcg & 15;
    stage32k(sb + (buf ? OFF_B1 : OFF_B0), &g_Wm[k2][hc][0][0], tid);
    if (tid < 16)
        cp16(sb + OFF_BB + buf * 256 + tid * 16,
             (const char*)&g_bdre[k2][hc][0] + tid * 16);
}

__global__ __launch_bounds__(NTH, 2)
void sylv_main(const float* __restrict__ z0, const float* __restrict__ h,
               float* __restrict__ out_z, float* __restrict__ out_ld)
{
    extern __shared__ char sm[];
    const uint32_t sb = smem_u32(sm);
    float* zsm = (float*)(sm + OFF_Z);

    const int tid = threadIdx.x, w = tid >> 5, lane = tid & 31;
    const int g = lane >> 2, t = lane & 3;
    const int r0 = (w & 3) * 16;           // GEMM row base (4 M-tiles)
    const int nq = w >> 2;                 // GEMM col half (0/1) of the 64 cols
    const int blk = blockIdx.x;
    const int m0 = blk * TM;
    const int msamp = tid >> 2, q = tid & 3;   // flow: sample / quarter (8 i's)

    // ---- A fragments (persist): split bf16 hi/lo ----
    uint32_t aH[8][4], aL[8][4];
    {
        const float* hp = h + (size_t)m0 * HH;
        #pragma unroll
        for (int ks = 0; ks < 8; ks++) {
            int k0 = ks * 16 + 2 * t;
            const float* p0 = hp + (size_t)(r0 + g) * HH + k0;
            const float* p1 = hp + (size_t)(r0 + g + 8) * HH + k0;
            float2 x0 = *(const float2*)p0;
            float2 x1 = *(const float2*)p1;
            float2 x2 = *(const float2*)(p0 + 8);
            float2 x3 = *(const float2*)(p1 + 8);
            aH[ks][0] = pack2(x0.x, x0.y); aL[ks][0] = pack2(bres(x0.x), bres(x0.y));
            aH[ks][1] = pack2(x1.x, x1.y); aL[ks][1] = pack2(bres(x1.x), bres(x1.y));
            aH[ks][2] = pack2(x2.x, x2.y); aL[ks][2] = pack2(bres(x2.x), bres(x2.y));
            aH[ks][3] = pack2(x3.x, x3.y); aL[ks][3] = pack2(bres(x3.x), bres(x3.y));
        }
    }
    // ---- z into smem ----
    for (int idx = tid; idx < TM * ZZ; idx += NTH)
        zsm[(idx >> 5) * 33 + (idx & 31)] = z0[(size_t)(m0 + (idx >> 5)) * ZZ + (idx & 31)];

    const uint4* BqA = (const uint4*)(sm + OFF_B0);
    const uint4* BqB = (const uint4*)(sm + OFF_B1);

    // ---- diag GEMMs (6 half-chunks, double-buffered) -> global scratch ----
    stage32k(sb + OFF_B0, &g_Wg[0][0][0][0], tid);
    CP_COMMIT();
    for (int d = 0; d < 6; d++) {
        if (d < 5) {
            int dn = d + 1;
            stage32k(sb + ((dn & 1) ? OFF_B1 : OFF_B0), &g_Wg[dn >> 1][dn & 1][0][0], tid);
            CP_COMMIT(); CP_WAIT1();
        } else {
            CP_WAIT0();
        }
        __syncthreads();
        {
            int mm = d >> 1, half = d & 1;
            float acc[4][4];
            gemm_h((d & 1) ? BqB : BqA, lane, nq, aH, aL, acc);
            #pragma unroll
            for (int ntl = 0; ntl < 4; ntl++) {
                int lc = nq * 32 + ntl * 8 + 2 * t;
                int n = half * 64 + lc;
                float b0v = g_bdiag[mm][n], b1v = g_bdiag[mm][n + 1];
                float v0 = acc[ntl][0] + b0v, v1 = acc[ntl][1] + b1v;
                float v2 = acc[ntl][2] + b0v, v3 = acc[ntl][3] + b1v;
                if (mm < 2) { v0 = tanhf(v0); v1 = tanhf(v1); v2 = tanhf(v2); v3 = tanhf(v3); }
                g_dg[blk][mm][n][r0 + g]         = v0;
                g_dg[blk][mm][n + 1][r0 + g]     = v1;
                g_dg[blk][mm][n][r0 + g + 8]     = v2;
                g_dg[blk][mm][n + 1][r0 + g + 8] = v3;
            }
        }
        __syncthreads();
    }

    // ---- prologue: stage half-chunks 0,1; GEMM 0 -> D0 ----
    stage_main(sb, 0, 0, tid);
    stage_main(sb, 1, 1, tid);
    CP_COMMIT(); CP_WAIT0();
    __syncthreads();
    {
        float acc[4][4];
        gemm_h(BqA, lane, nq, aH, aL, acc);
        float* Dd = (float*)(sm + OFF_D0);
        const float* bbp = (const float*)(sm + OFF_BB);
        #pragma unroll
        for (int ntl = 0; ntl < 4; ntl++) {
            int n0 = nq * 32 + ntl * 8 + 2 * t;
            float b0v = bbp[n0], b1v = bbp[n0 + 1];
            *(float2*)&Dd[(r0 + g) * DP + n0]     = make_float2(acc[ntl][0] + b0v, acc[ntl][1] + b1v);
            *(float2*)&Dd[(r0 + g + 8) * DP + n0] = make_float2(acc[ntl][2] + b0v, acc[ntl][3] + b1v);
        }
    }
    __syncthreads();

    // ---- diag prefetch for cc=0 (j0=0, j1=1) ----
    float pf_d1[2], pf_d2[2], pf_b[2];
    pf_d1[0] = g_dg[blk][0][0][msamp]; pf_d1[1] = g_dg[blk][0][1][msamp];
    pf_d2[0] = g_dg[blk][1][0][msamp]; pf_d2[1] = g_dg[blk][1][1][msamp];
    pf_b[0]  = g_dg[blk][2][0][msamp]; pf_b[1]  = g_dg[blk][2][1][msamp];

    // ---- main loop over 64 half-chunks ----
    float zp[8], dz[8], ld_acc = 0.f;

    #pragma unroll 1
    for (int cc = 0; cc < 64; cc++) {
        const int k = cc >> 4, hc = cc & 15, flip = k & 1;
        const int nx = cc + 1;
        const int j0 = hc * 2, j1 = j0 + 1;

        // consume prefetched diag; issue prefetch for cc+1
        float d1v0 = pf_d1[0], d1v1 = pf_d1[1];
        float d2v0 = pf_d2[0], d2v1 = pf_d2[1];
        float bv0 = pf_b[0], bv1 = pf_b[1];
        if (nx < 64) {
            int kjn = (nx >> 4) * 32 + (nx & 15) * 2;
            pf_d1[0] = g_dg[blk][0][kjn][msamp];     pf_d1[1] = g_dg[blk][0][kjn + 1][msamp];
            pf_d2[0] = g_dg[blk][1][kjn][msamp];     pf_d2[1] = g_dg[blk][1][kjn + 1][msamp];
            pf_b[0]  = g_dg[blk][2][kjn][msamp];     pf_b[1]  = g_dg[blk][2][kjn + 1][msamp];
        }

        // stage half-chunk cc+2 under the MMAs
        if (cc <= 61) stage_main(sb, cc & 1, cc + 2, tid);

        // GEMM half-chunk nx; store immediately (acc dies before flow)
        if (nx < 64) {
            float acc[4][4];
            gemm_h((nx & 1) ? BqB : BqA, lane, nq, aH, aL, acc);
            float* Dd = (float*)(sm + ((nx & 1) ? OFF_D1 : OFF_D0));
            const float* bbp = (const float*)(sm + OFF_BB + (nx & 1) * 256);
            #pragma unroll
            for (int ntl = 0; ntl < 4; ntl++) {
                int n0 = nq * 32 + ntl * 8 + 2 * t;
                float b0v = bbp[n0], b1v = bbp[n0 + 1];
                *(float2*)&Dd[(r0 + g) * DP + n0]     = make_float2(acc[ntl][0] + b0v, acc[ntl][1] + b1v);
                *(float2*)&Dd[(r0 + g + 8) * DP + n0] = make_float2(acc[ntl][2] + b0v, acc[ntl][3] + b1v);
            }
        }

        // ---- flow half-chunk cc (2 j's) ----
        {
            const float* Dc = (const float*)(sm + ((cc & 1) ? OFF_D1 : OFF_D0));
            if (hc == 0) {
                #pragma unroll
                for (int il = 0; il < 8; il++) {
                    int gi = q * 8 + il;
                    zp[il] = zsm[msamp * 33 + (flip ? 31 - gi : gi)];
                    dz[il] = 0.f;
                }
            }
            float zpj0 = zsm[msamp * 33 + (flip ? 31 - j0 : j0)];
            float zpj1 = zsm[msamp * 33 + (flip ? 31 - j1 : j1)];

            float Dv[2][8];
            #pragma unroll
            for (int jj = 0; jj < 2; jj++) {
                const float4* p = (const float4*)&Dc[msamp * DP + jj * 32 + q * 8];
                float4 x = p[0], y = p[1];
                Dv[jj][0] = x.x; Dv[jj][1] = x.y; Dv[jj][2] = x.z; Dv[jj][3] = x.w;
                Dv[jj][4] = y.x; Dv[jj][5] = y.y; Dv[jj][6] = y.z; Dv[jj][7] = y.w;
            }
            float p0 = 0.f, p1 = 0.f;
            #pragma unroll
            for (int il = 0; il < 8; il++) {
                int gi = q * 8 + il;
                p0 = fmaf(zp[il], (gi > j0) ? Dv[0][il] : 0.f, p0);
                p1 = fmaf(zp[il], (gi > j1) ? Dv[1][il] : 0.f, p1);
            }
            p0 += __shfl_xor_sync(0xffffffffu, p0, 1);
            p0 += __shfl_xor_sync(0xffffffffu, p0, 2);
            p1 += __shfl_xor_sync(0xffffffffu, p1, 1);
            p1 += __shfl_xor_sync(0xffffffffu, p1, 2);
            float t0 = tanhf(p0 + bv0 + zpj0 * d2v0);
            float t1 = tanhf(p1 + bv1 + zpj1 * d2v1);
            if (q == 0) {
                ld_acc += logf(fabsf(fmaf(1.f - t0 * t0, d1v0 * d2v0, 1.f)));
                ld_acc += logf(fabsf(fmaf(1.f - t1 * t1, d1v1 * d2v1, 1.f)));
            }
            #pragma unroll
            for (int il = 0; il < 8; il++) {
                int gi = q * 8 + il;
                float c0 = (gi < j0) ? Dv[0][il] : ((gi == j0) ? d1v0 : 0.f);
                float c1 = (gi < j1) ? Dv[1][il] : ((gi == j1) ? d1v1 : 0.f);
                dz[il] = fmaf(t0, c0, fmaf(t1, c1, dz[il]));
            }
            if (hc == 15) {
                #pragma unroll
                for (int il = 0; il < 8; il++) {
                    int gi = q * 8 + il;
                    zsm[msamp * 33 + (flip ? 31 - gi : gi)] += dz[il];
                }
            }
        }

        CP_COMMIT(); CP_WAIT0();
        __syncthreads();
    }

    // ---- outputs ----
    if (q == 0) out_ld[m0 + msamp] = ld_acc;
    for (int idx = tid; idx < TM * ZZ; idx += NTH)
        out_z[(size_t)(m0 + (idx >> 5)) * ZZ + (idx & 31)] = zsm[(idx >> 5) * 33 + (idx & 31)];
}

extern "C" void kernel_launch(void* const* d_in, const int* in_sizes, int n_in,
                              void* d_out, int out_size)
{
    const float* z0  = (const float*)d_in[0];
    const float* h   = (const float*)d_in[1];
    const float* Wd  = (const float*)d_in[2];
    const float* bd  = (const float*)d_in[3];
    const float* Wd1 = (const float*)d_in[4];
    const float* bd1 = (const float*)d_in[5];
    const float* Wd2 = (const float*)d_in[6];
    const float* bd2 = (const float*)d_in[7];
    const float* Wb  = (const float*)d_in[8];
    const float* bb  = (const float*)d_in[9];

    const int B = in_sizes[0] / ZZ;          // 32768
    float* out_z  = (float*)d_out;
    float* out_ld = (float*)d_out + (size_t)B * ZZ;

    int prep_elems = 131072 + 12288 + 4096 + 384;
    prep_kernel<<<(prep_elems + 255) / 256, 256>>>(Wd, bd, Wd1, bd1, Wd2, bd2, Wb, bb);

    cudaFuncSetAttribute(sylv_main, cudaFuncAttributeMaxDynamicSharedMemorySize, SMEM_TOTAL);
    sylv_main<<<B / TM, NTH, SMEM_TOTAL>>>(z0, h, out_z, out_ld);
}

// round 12
// speedup vs baseline: 1.6943x; 1.0004x over previous
#include <cuda_runtime.h>
#include <cuda_bf16.h>
#include <stdint.h>
#include <math.h>

// TriangularSylvesterNeRF  Z=32 K=4 H=128 B=32768
// mma.sync bf16 split-precision; 64-col half-chunks; 2 CTAs/SM (smem 107KB, regs<=128).

#define ZZ 32
#define KK 4
#define HH 128
#define TM 64
#define NTH 256
#define NCTA 512
#define DP 68            /* D row pitch (floats) */

// ---- smem byte offsets ----
#define OFF_B0 0         /* 32KB interleaved hi/lo */
#define OFF_B1 32768
#define OFF_D0 65536     /* [64][68] f32 = 17408 */
#define OFF_D1 82944
#define OFF_Z  100352    /* [64][33] f32 = 8448 */
#define OFF_BB 108800    /* bias slots [2][64] f32 */
#define SMEM_TOTAL 109312

// ---- fragment-linear weight images, interleaved {hi.x,hi.y,lo.x,lo.y} ----
// main: [k][half-chunk hc 0..15][slot = ks*8+ntl][lane]; cols n = hc*64 + ntl*8 + g,
// global n-ordering n = j*32 + i  (j = n>>5, i = n&31)
__device__ uint4 g_Wm[KK][16][64][32];
__device__ uint4 g_Wg[3][2][64][32];
__device__ __align__(16) float g_bdre[KK][16][64];
__device__ float g_bdiag[3][128];
// per-CTA diag scratch: [blk][{d1,d2,b}][kj 0..127][sample 0..63]
__device__ float g_dg[NCTA][3][128][64];

__device__ __forceinline__ uint32_t pack2(float a, float b) {
    return (uint32_t)__bfloat16_as_ushort(__float2bfloat16(a)) |
           ((uint32_t)__bfloat16_as_ushort(__float2bfloat16(b)) << 16);
}
__device__ __forceinline__ float bres(float x) {
    return x - __bfloat162float(__float2bfloat16(x));
}

__global__ void prep_kernel(const float* __restrict__ Wd, const float* __restrict__ bd,
                            const float* __restrict__ Wd1, const float* __restrict__ bd1,
                            const float* __restrict__ Wd2, const float* __restrict__ bd2,
                            const float* __restrict__ Wb, const float* __restrict__ bb)
{
    int idx = blockIdx.x * blockDim.x + threadIdx.x;
    if (idx < 131072) {                      // main weights
        int lane = idx & 31, slot = (idx >> 5) & 63, hc = (idx >> 11) & 15, k = idx >> 15;
        int ks = slot >> 3, ntl = slot & 7, g = lane >> 2, t = lane & 3;
        int n = hc * 64 + ntl * 8 + g;
        int j = n >> 5, i = n & 31;
        const float* src = Wd + (size_t)((i * ZZ + j) * KK + k) * HH + ks * 16 + 2 * t;
        float f0 = src[0], f1 = src[1], f2 = src[8], f3 = src[9];
        g_Wm[k][hc][slot][lane] = make_uint4(pack2(f0, f1), pack2(f2, f3),
                                             pack2(bres(f0), bres(f1)),
                                             pack2(bres(f2), bres(f3)));
    } else if (idx < 131072 + 12288) {       // diag weights
        int r = idx - 131072;
        int lane = r & 31, slot = (r >> 5) & 63, half = (r >> 11) & 1, m = r >> 12;
        int ks = slot >> 3, ntl = slot & 7, g = lane >> 2, t = lane & 3;
        int n = half * 64 + ntl * 8 + g;     // n = kq*32 + j
        int kq = n >> 5, j = n & 31;
        const float* W = (m == 0) ? Wd1 : (m == 1) ? Wd2 : Wb;
        const float* src = W + (size_t)(j * KK + kq) * HH + ks * 16 + 2 * t;
        float f0 = src[0], f1 = src[1], f2 = src[8], f3 = src[9];
        g_Wg[m][half][slot][lane] = make_uint4(pack2(f0, f1), pack2(f2, f3),
                                               pack2(bres(f0), bres(f1)),
                                               pack2(bres(f2), bres(f3)));
    } else if (idx < 131072 + 12288 + 4096) {  // main biases [k][hc][64]
        int r = idx - 131072 - 12288;
        int l = r & 63, hc = (r >> 6) & 15, k = r >> 10;
        int n = hc * 64 + l;
        int j = n >> 5, i = n & 31;
        g_bdre[k][hc][l] = bd[(i * ZZ + j) * KK + k];
    } else if (idx < 131072 + 12288 + 4096 + 384) {  // diag biases [m][kj]
        int r = idx - 147456;
        int n = r & 127, m = r >> 7;
        int kq = n >> 5, j = n & 31;
        const float* bv = (m == 0) ? bd1 : (m == 1) ? bd2 : bb;
        g_bdiag[m][n] = bv[j * KK + kq];
    }
}

__device__ __forceinline__ void mma_bf16(float c[4], const uint32_t a[4],
                                         uint32_t b0, uint32_t b1) {
    asm volatile(
        "mma.sync.aligned.m16n8k16.row.col.f32.bf16.bf16.f32 "
        "{%0,%1,%2,%3}, {%4,%5,%6,%7}, {%8,%9}, {%0,%1,%2,%3};"
        : "+f"(c[0]), "+f"(c[1]), "+f"(c[2]), "+f"(c[3])
        : "r"(a[0]), "r"(a[1]), "r"(a[2]), "r"(a[3]), "r"(b0), "r"(b1));
}
__device__ __forceinline__ void cp16(uint32_t dst, const void* src) {
    asm volatile("cp.async.cg.shared.global [%0], [%1], 16;" :: "r"(dst), "l"(src));
}
#define CP_COMMIT() asm volatile("cp.async.commit_group;" ::: "memory")
#define CP_WAIT0()  asm volatile("cp.async.wait_group 0;" ::: "memory")
#define CP_WAIT1()  asm volatile("cp.async.wait_group 1;" ::: "memory")

__device__ __forceinline__ uint32_t smem_u32(const void* p) {
    uint32_t a;
    asm("{ .reg .u64 t; cvta.to.shared.u64 t, %1; cvt.u32.u64 %0, t; }" : "=r"(a) : "l"(p));
    return a;
}

// Half-chunk GEMM: warp tile 16 rows x 32 cols, quad-interleaved MMA order.
__device__ __forceinline__ void gemm_h(const uint4* __restrict__ Bq,
                                       int lane, int nq,
                                       const uint32_t aH[8][4],
                                       const uint32_t aL[8][4],
                                       float acc[4][4])
{
    #pragma unroll
    for (int q = 0; q < 4; q++)
        acc[q][0] = acc[q][1] = acc[q][2] = acc[q][3] = 0.f;
    #pragma unroll
    for (int ks = 0; ks < 8; ks++) {
        const int base = ks * 8 + nq * 4;
        uint4 b0 = Bq[(base + 0) * 32 + lane];
        uint4 b1 = Bq[(base + 1) * 32 + lane];
        uint4 b2 = Bq[(base + 2) * 32 + lane];
        uint4 b3 = Bq[(base + 3) * 32 + lane];
        mma_bf16(acc[0], aH[ks], b0.x, b0.y);
        mma_bf16(acc[1], aH[ks], b1.x, b1.y);
        mma_bf16(acc[2], aH[ks], b2.x, b2.y);
        mma_bf16(acc[3], aH[ks], b3.x, b3.y);
        mma_bf16(acc[0], aH[ks], b0.z, b0.w);
        mma_bf16(acc[1], aH[ks], b1.z, b1.w);
        mma_bf16(acc[2], aH[ks], b2.z, b2.w);
        mma_bf16(acc[3], aH[ks], b3.z, b3.w);
        mma_bf16(acc[0], aL[ks], b0.x, b0.y);
        mma_bf16(acc[1], aL[ks], b1.x, b1.y);
        mma_bf16(acc[2], aL[ks], b2.x, b2.y);
        mma_bf16(acc[3], aL[ks], b3.x, b3.y);
    }
}

// stage 32KB (2048 uint4) to smem buffer
__device__ __forceinline__ void stage32k(uint32_t dst, const void* srcv, int tid) {
    const char* s = (const char*)srcv;
    #pragma unroll
    for (int r = 0; r < 8; r++) {
        int i = r * NTH + tid;
        cp16(dst + i * 16, s + i * 16);
    }
}
// stage main half-chunk hcg (0..63) + its bias into buffer `buf`
__device__ __forceinline__ void stage_main(uint32_t sb, int buf, int hcg, int tid) {
    int k2 = hcg >> 4, hc = hcg & 15;
    stage32k(sb + (buf ? OFF_B1 : OFF_B0), &g_Wm[k2][hc][0][0], tid);
    if (tid < 16)
        cp16(sb + OFF_BB + buf * 256 + tid * 16,
             (const char*)&g_bdre[k2][hc][0] + tid * 16);
}

__global__ __launch_bounds__(NTH, 2)
void sylv_main(const float* __restrict__ z0, const float* __restrict__ h,
               float* __restrict__ out_z, float* __restrict__ out_ld)
{
    extern __shared__ char sm[];
    const uint32_t sb = smem_u32(sm);
    float* zsm = (float*)(sm + OFF_Z);

    const int tid = threadIdx.x, w = tid >> 5, lane = tid & 31;
    const int g = lane >> 2, t = lane & 3;
    const int r0 = (w & 3) * 16;           // GEMM row base (4 M-tiles)
    const int nq = w >> 2;                 // GEMM col half (0/1) of the 64 cols
    const int blk = blockIdx.x;
    const int m0 = blk * TM;
    const int msamp = tid >> 2, q = tid & 3;   // flow: sample / quarter (8 i's)

    // ---- A fragments (persist): split bf16 hi/lo ----
    uint32_t aH[8][4], aL[8][4];
    {
        const float* hp = h + (size_t)m0 * HH;
        #pragma unroll
        for (int ks = 0; ks < 8; ks++) {
            int k0 = ks * 16 + 2 * t;
            const float* p0 = hp + (size_t)(r0 + g) * HH + k0;
            const float* p1 = hp + (size_t)(r0 + g + 8) * HH + k0;
            float2 x0 = *(const float2*)p0;
            float2 x1 = *(const float2*)p1;
            float2 x2 = *(const float2*)(p0 + 8);
            float2 x3 = *(const float2*)(p1 + 8);
            aH[ks][0] = pack2(x0.x, x0.y); aL[ks][0] = pack2(bres(x0.x), bres(x0.y));
            aH[ks][1] = pack2(x1.x, x1.y); aL[ks][1] = pack2(bres(x1.x), bres(x1.y));
            aH[ks][2] = pack2(x2.x, x2.y); aL[ks][2] = pack2(bres(x2.x), bres(x2.y));
            aH[ks][3] = pack2(x3.x, x3.y); aL[ks][3] = pack2(bres(x3.x), bres(x3.y));
        }
    }
    // ---- z into smem ----
    for (int idx = tid; idx < TM * ZZ; idx += NTH)
        zsm[(idx >> 5) * 33 + (idx & 31)] = z0[(size_t)(m0 + (idx >> 5)) * ZZ + (idx & 31)];

    const uint4* BqA = (const uint4*)(sm + OFF_B0);
    const uint4* BqB = (const uint4*)(sm + OFF_B1);

    // ---- diag GEMMs (6 half-chunks, double-buffered) -> global scratch ----
    stage32k(sb + OFF_B0, &g_Wg[0][0][0][0], tid);
    CP_COMMIT();
    for (int d = 0; d < 6; d++) {
        if (d < 5) {
            int dn = d + 1;
            stage32k(sb + ((dn & 1) ? OFF_B1 : OFF_B0), &g_Wg[dn >> 1][dn & 1][0][0], tid);
            CP_COMMIT(); CP_WAIT1();
        } else {
            CP_WAIT0();
        }
        __syncthreads();
        {
            int mm = d >> 1, half = d & 1;
            float acc[4][4];
            gemm_h((d & 1) ? BqB : BqA, lane, nq, aH, aL, acc);
            #pragma unroll
            for (int ntl = 0; ntl < 4; ntl++) {
                int lc = nq * 32 + ntl * 8 + 2 * t;
                int n = half * 64 + lc;
                float b0v = g_bdiag[mm][n], b1v = g_bdiag[mm][n + 1];
                float v0 = acc[ntl][0] + b0v, v1 = acc[ntl][1] + b1v;
                float v2 = acc[ntl][2] + b0v, v3 = acc[ntl][3] + b1v;
                if (mm < 2) { v0 = tanhf(v0); v1 = tanhf(v1); v2 = tanhf(v2); v3 = tanhf(v3); }
                g_dg[blk][mm][n][r0 + g]         = v0;
                g_dg[blk][mm][n + 1][r0 + g]     = v1;
                g_dg[blk][mm][n][r0 + g + 8]     = v2;
                g_dg[blk][mm][n + 1][r0 + g + 8] = v3;
            }
        }
        __syncthreads();
    }

    // ---- prologue: stage half-chunks 0,1; GEMM 0 -> D0 ----
    stage_main(sb, 0, 0, tid);
    stage_main(sb, 1, 1, tid);
    CP_COMMIT(); CP_WAIT0();
    __syncthreads();
    {
        float acc[4][4];
        gemm_h(BqA, lane, nq, aH, aL, acc);
        float* Dd = (float*)(sm + OFF_D0);
        const float* bbp = (const float*)(sm + OFF_BB);
        #pragma unroll
        for (int ntl = 0; ntl < 4; ntl++) {
            int n0 = nq * 32 + ntl * 8 + 2 * t;
            float b0v = bbp[n0], b1v = bbp[n0 + 1];
            *(float2*)&Dd[(r0 + g) * DP + n0]     = make_float2(acc[ntl][0] + b0v, acc[ntl][1] + b1v);
            *(float2*)&Dd[(r0 + g + 8) * DP + n0] = make_float2(acc[ntl][2] + b0v, acc[ntl][3] + b1v);
        }
    }
    __syncthreads();

    // ---- diag prefetch for cc=0 (j0=0, j1=1) ----
    float pf_d1[2], pf_d2[2], pf_b[2];
    pf_d1[0] = g_dg[blk][0][0][msamp]; pf_d1[1] = g_dg[blk][0][1][msamp];
    pf_d2[0] = g_dg[blk][1][0][msamp]; pf_d2[1] = g_dg[blk][1][1][msamp];
    pf_b[0]  = g_dg[blk][2][0][msamp]; pf_b[1]  = g_dg[blk][2][1][msamp];

    // ---- main loop over 64 half-chunks ----
    float zp[8], dz[8], ld_acc = 0.f;

    #pragma unroll 1
    for (int cc = 0; cc < 64; cc++) {
        const int k = cc >> 4, hc = cc & 15, flip = k & 1;
        const int nx = cc + 1;
        const int j0 = hc * 2, j1 = j0 + 1;

        // consume prefetched diag; issue prefetch for cc+1
        float d1v0 = pf_d1[0], d1v1 = pf_d1[1];
        float d2v0 = pf_d2[0], d2v1 = pf_d2[1];
        float bv0 = pf_b[0], bv1 = pf_b[1];
        if (nx < 64) {
            int kjn = (nx >> 4) * 32 + (nx & 15) * 2;
            pf_d1[0] = g_dg[blk][0][kjn][msamp];     pf_d1[1] = g_dg[blk][0][kjn + 1][msamp];
            pf_d2[0] = g_dg[blk][1][kjn][msamp];     pf_d2[1] = g_dg[blk][1][kjn + 1][msamp];
            pf_b[0]  = g_dg[blk][2][kjn][msamp];     pf_b[1]  = g_dg[blk][2][kjn + 1][msamp];
        }

        // stage half-chunk cc+2 under the MMAs
        if (cc <= 61) stage_main(sb, cc & 1, cc + 2, tid);

        // GEMM half-chunk nx; store immediately (acc dies before flow)
        if (nx < 64) {
            float acc[4][4];
            gemm_h((nx & 1) ? BqB : BqA, lane, nq, aH, aL, acc);
            float* Dd = (float*)(sm + ((nx & 1) ? OFF_D1 : OFF_D0));
            const float* bbp = (const float*)(sm + OFF_BB + (nx & 1) * 256);
            #pragma unroll
            for (int ntl = 0; ntl < 4; ntl++) {
                int n0 = nq * 32 + ntl * 8 + 2 * t;
                float b0v = bbp[n0], b1v = bbp[n0 + 1];
                *(float2*)&Dd[(r0 + g) * DP + n0]     = make_float2(acc[ntl][0] + b0v, acc[ntl][1] + b1v);
                *(float2*)&Dd[(r0 + g + 8) * DP + n0] = make_float2(acc[ntl][2] + b0v, acc[ntl][3] + b1v);
            }
        }

        // ---- flow half-chunk cc (2 j's) ----
        {
            const float* Dc = (const float*)(sm + ((cc & 1) ? OFF_D1 : OFF_D0));
            if (hc == 0) {
                #pragma unroll
                for (int il = 0; il < 8; il++) {
                    int gi = q * 8 + il;
                    zp[il] = zsm[msamp * 33 + (flip ? 31 - gi : gi)];
                    dz[il] = 0.f;
                }
            }
            float zpj0 = zsm[msamp * 33 + (flip ? 31 - j0 : j0)];
            float zpj1 = zsm[msamp * 33 + (flip ? 31 - j1 : j1)];

            float Dv[2][8];
            #pragma unroll
            for (int jj = 0; jj < 2; jj++) {
                const float4* p = (const float4*)&Dc[msamp * DP + jj * 32 + q * 8];
                float4 x = p[0], y = p[1];
                Dv[jj][0] = x.x; Dv[jj][1] = x.y; Dv[jj][2] = x.z; Dv[jj][3] = x.w;
                Dv[jj][4] = y.x; Dv[jj][5] = y.y; Dv[jj][6] = y.z; Dv[jj][7] = y.w;
            }
            float p0 = 0.f, p1 = 0.f;
            #pragma unroll
            for (int il = 0; il < 8; il++) {
                int gi = q * 8 + il;
                p0 = fmaf(zp[il], (gi > j0) ? Dv[0][il] : 0.f, p0);
                p1 = fmaf(zp[il], (gi > j1) ? Dv[1][il] : 0.f, p1);
            }
            p0 += __shfl_xor_sync(0xffffffffu, p0, 1);
            p0 += __shfl_xor_sync(0xffffffffu, p0, 2);
            p1 += __shfl_xor_sync(0xffffffffu, p1, 1);
            p1 += __shfl_xor_sync(0xffffffffu, p1, 2);
            float t0 = tanhf(p0 + bv0 + zpj0 * d2v0);
            float t1 = tanhf(p1 + bv1 + zpj1 * d2v1);
            if (q == 0) {
                ld_acc += logf(fabsf(fmaf(1.f - t0 * t0, d1v0 * d2v0, 1.f)));
                ld_acc += logf(fabsf(fmaf(1.f - t1 * t1, d1v1 * d2v1, 1.f)));
            }
            #pragma unroll
            for (int il = 0; il < 8; il++) {
                int gi = q * 8 + il;
                float c0 = (gi < j0) ? Dv[0][il] : ((gi == j0) ? d1v0 : 0.f);
                float c1 = (gi < j1) ? Dv[1][il] : ((gi == j1) ? d1v1 : 0.f);
                dz[il] = fmaf(t0, c0, fmaf(t1, c1, dz[il]));
            }
            if (hc == 15) {
                #pragma unroll
                for (int il = 0; il < 8; il++) {
                    int gi = q * 8 + il;
                    zsm[msamp * 33 + (flip ? 31 - gi : gi)] += dz[il];
                }
            }
        }

        CP_COMMIT(); CP_WAIT0();
        __syncthreads();
    }

    // ---- outputs ----
    if (q == 0) out_ld[m0 + msamp] = ld_acc;
    for (int idx = tid; idx < TM * ZZ; idx += NTH)
        out_z[(size_t)(m0 + (idx >> 5)) * ZZ + (idx & 31)] = zsm[(idx >> 5) * 33 + (idx & 31)];
}

extern "C" void kernel_launch(void* const* d_in, const int* in_sizes, int n_in,
                              void* d_out, int out_size)
{
    const float* z0  = (const float*)d_in[0];
    const float* h   = (const float*)d_in[1];
    const float* Wd  = (const float*)d_in[2];
    const float* bd  = (const float*)d_in[3];
    const float* Wd1 = (const float*)d_in[4];
    const float* bd1 = (const float*)d_in[5];
    const float* Wd2 = (const float*)d_in[6];
    const float* bd2 = (const float*)d_in[7];
    const float* Wb  = (const float*)d_in[8];
    const float* bb  = (const float*)d_in[9];

    const int B = in_sizes[0] / ZZ;          // 32768
    float* out_z  = (float*)d_out;
    float* out_ld = (float*)d_out + (size_t)B * ZZ;

    int prep_elems = 131072 + 12288 + 4096 + 384;
    prep_kernel<<<(prep_elems + 255) / 256, 256>>>(Wd, bd, Wd1, bd1, Wd2, bd2, Wb, bb);

    cudaFuncSetAttribute(sylv_main, cudaFuncAttributeMaxDynamicSharedMemorySize, SMEM_TOTAL);
    sylv_main<<<B / TM, NTH, SMEM_TOTAL>>>(z0, h, out_z, out_ld);
}